// round 1
// baseline (speedup 1.0000x reference)
#include <cuda_runtime.h>
#include <cuda_bf16.h>
#include <math.h>

// Problem constants
constexpr int B  = 2;
constexpr int S  = 1024;
constexpr int V  = 32000;
constexpr int D  = 1024;
constexpr int DH = 4096;
constexpr int NL = 4;
constexpr int NH = 16;
constexpr int HD = 64;
constexpr int M  = B * S;          // 2048 rows everywhere

// ---------------------------------------------------------------------------
// Scratch (device globals — no allocations allowed)
// ---------------------------------------------------------------------------
__device__ float g_h[M * D];       // residual stream
__device__ float g_a[M * D];       // LN output / final LN
__device__ float g_q[M * D];
__device__ float g_k[M * D];
__device__ float g_v[M * D];
__device__ float g_t[M * D];       // attention output
__device__ float g_f[M * DH];      // FFN intermediate

// ---------------------------------------------------------------------------
// Embedding + positional encoding:  out[i,:] = emb[x[i],:] + pe[i%S,:]
// ---------------------------------------------------------------------------
__global__ void embed_kernel(const int* __restrict__ x,
                             const float* __restrict__ emb,
                             const float* __restrict__ pe,
                             float* __restrict__ out)
{
    const int i   = blockIdx.x;          // 0..M-1
    const int s   = i % S;
    const int tok = x[i];
    const float4* e = reinterpret_cast<const float4*>(emb + (size_t)tok * D);
    const float4* p = reinterpret_cast<const float4*>(pe  + (size_t)s   * D);
    float4*       o = reinterpret_cast<float4*>(out + (size_t)i * D);
    const int t = threadIdx.x;           // 256 threads, D/4 = 256
    float4 a = e[t], b = p[t];
    o[t] = make_float4(a.x + b.x, a.y + b.y, a.z + b.z, a.w + b.w);
}

// ---------------------------------------------------------------------------
// LayerNorm (row-wise, two-pass):  y = (x-mu)*rsqrt(var+eps)*g + b
// One block (256 threads) per row.
// ---------------------------------------------------------------------------
__global__ void ln_kernel(const float* __restrict__ X,
                          const float* __restrict__ gam,
                          const float* __restrict__ bet,
                          float* __restrict__ Y)
{
    const int row = blockIdx.x;
    const float* x = X + (size_t)row * D;
    float*       y = Y + (size_t)row * D;
    __shared__ float sred[8];
    const int tid = threadIdx.x;

    float s = 0.f;
    for (int d = tid; d < D; d += 256) s += x[d];
    #pragma unroll
    for (int o = 16; o > 0; o >>= 1) s += __shfl_xor_sync(0xffffffffu, s, o);
    if ((tid & 31) == 0) sred[tid >> 5] = s;
    __syncthreads();
    float mean = 0.f;
    #pragma unroll
    for (int w = 0; w < 8; w++) mean += sred[w];
    mean *= (1.0f / D);
    __syncthreads();

    float vs = 0.f;
    for (int d = tid; d < D; d += 256) { float t = x[d] - mean; vs += t * t; }
    #pragma unroll
    for (int o = 16; o > 0; o >>= 1) vs += __shfl_xor_sync(0xffffffffu, vs, o);
    if ((tid & 31) == 0) sred[tid >> 5] = vs;
    __syncthreads();
    float var = 0.f;
    #pragma unroll
    for (int w = 0; w < 8; w++) var += sred[w];
    var *= (1.0f / D);
    const float rstd = rsqrtf(var + 1e-5f);

    for (int d = tid; d < D; d += 256)
        y[d] = (x[d] - mean) * rstd * gam[d] + bet[d];
}

// ---------------------------------------------------------------------------
// SGEMM: C[M,N] = A[M,K] @ W[K,N]  (+bias[n]) (+res[m,n]) (relu)
// 128x128 block tile, BK=8, 8x8 per-thread microtile, 256 threads.
// All shapes divide tiles exactly (M=2048; N in {1024,4096,32000}; K in {1024,4096}).
// ---------------------------------------------------------------------------
template<bool HAS_BIAS, bool HAS_RES, bool RELU>
__global__ __launch_bounds__(256)
void sgemm128(int Mm, int N, int K,
              const float* __restrict__ A,
              const float* __restrict__ Bm,
              const float* __restrict__ bias,
              const float* __restrict__ res,
              float* __restrict__ C)
{
    constexpr int BM = 128, BN = 128, BK = 8, TM = 8, TN = 8;
    __shared__ float As[BK * BM];    // transposed A tile
    __shared__ float Bs[BK * BN];

    const int cRow = blockIdx.y;
    const int cCol = blockIdx.x;
    const int tid  = threadIdx.x;
    const int threadCol = tid % (BN / TN);   // 0..15
    const int threadRow = tid / (BN / TN);   // 0..15

    A  += (size_t)cRow * BM * K;
    Bm += cCol * BN;

    const int innerRowA = tid >> 1;          // BK/4 = 2 float4 per row
    const int innerColA = (tid & 1) * 4;
    const int innerRowB = tid >> 5;          // BN/4 = 32
    const int innerColB = (tid & 31) * 4;

    float acc[TM * TN] = {0.f};
    float regM[TM], regN[TN];

    for (int k0 = 0; k0 < K; k0 += BK) {
        float4 a4 = *reinterpret_cast<const float4*>(&A[(size_t)innerRowA * K + innerColA]);
        As[(innerColA + 0) * BM + innerRowA] = a4.x;
        As[(innerColA + 1) * BM + innerRowA] = a4.y;
        As[(innerColA + 2) * BM + innerRowA] = a4.z;
        As[(innerColA + 3) * BM + innerRowA] = a4.w;
        *reinterpret_cast<float4*>(&Bs[innerRowB * BN + innerColB]) =
            *reinterpret_cast<const float4*>(&Bm[(size_t)innerRowB * N + innerColB]);
        __syncthreads();
        A  += BK;
        Bm += (size_t)BK * N;
        #pragma unroll
        for (int dot = 0; dot < BK; ++dot) {
            #pragma unroll
            for (int i = 0; i < TM; i++) regM[i] = As[dot * BM + threadRow * TM + i];
            #pragma unroll
            for (int j = 0; j < TN; j++) regN[j] = Bs[dot * BN + threadCol * TN + j];
            #pragma unroll
            for (int i = 0; i < TM; i++)
                #pragma unroll
                for (int j = 0; j < TN; j++)
                    acc[i * TN + j] += regM[i] * regN[j];
        }
        __syncthreads();
    }

    const size_t crow0 = (size_t)cRow * BM + threadRow * TM;
    const int    ccol0 = cCol * BN + threadCol * TN;
    #pragma unroll
    for (int i = 0; i < TM; i++) {
        const size_t base = (crow0 + i) * (size_t)N + ccol0;
        #pragma unroll
        for (int j = 0; j < TN; j++) {
            float val = acc[i * TN + j];
            if (HAS_BIAS) val += bias[ccol0 + j];
            if (HAS_RES)  val += res[base + j];
            if (RELU)     val = fmaxf(val, 0.f);
            C[base + j] = val;
        }
    }
}

// ---------------------------------------------------------------------------
// Causal attention. Q/K/V stored [B,S,D] with head h at columns [h*64, h*64+64).
// One block (128 threads) per (q, h, b). Scores kept in 4KB smem.
// scale = 1/sqrt(D) = 1/32 (source scales by sqrt(d_model), per reference).
// ---------------------------------------------------------------------------
__global__ __launch_bounds__(128)
void attn_kernel(const float* __restrict__ Q, const float* __restrict__ K,
                 const float* __restrict__ Vv, float* __restrict__ O)
{
    const int q = blockIdx.x, h = blockIdx.y, b = blockIdx.z;
    const int tid = threadIdx.x;
    __shared__ float sc[S];
    __shared__ float qs[HD];
    __shared__ float sred[4];
    __shared__ float o2[128];

    const size_t base = (size_t)b * S * D + (size_t)h * HD;
    if (tid < HD) qs[tid] = Q[base + (size_t)q * D + tid];
    __syncthreads();

    const int n = q + 1;
    const float scale = 0.03125f;    // 1/sqrt(1024)

    float m = -INFINITY;
    for (int j = tid; j < n; j += 128) {
        const float* kp = K + base + (size_t)j * D;
        float s = 0.f;
        #pragma unroll
        for (int d = 0; d < HD; d++) s += qs[d] * kp[d];
        s *= scale;
        sc[j] = s;
        m = fmaxf(m, s);
    }
    #pragma unroll
    for (int o = 16; o > 0; o >>= 1) m = fmaxf(m, __shfl_xor_sync(0xffffffffu, m, o));
    if ((tid & 31) == 0) sred[tid >> 5] = m;
    __syncthreads();
    m = fmaxf(fmaxf(sred[0], sred[1]), fmaxf(sred[2], sred[3]));
    __syncthreads();

    float sum = 0.f;
    for (int j = tid; j < n; j += 128) {
        float e = __expf(sc[j] - m);
        sc[j] = e;
        sum += e;
    }
    #pragma unroll
    for (int o = 16; o > 0; o >>= 1) sum += __shfl_xor_sync(0xffffffffu, sum, o);
    if ((tid & 31) == 0) sred[tid >> 5] = sum;
    __syncthreads();             // also publishes all sc[] exp writes
    sum = sred[0] + sred[1] + sred[2] + sred[3];
    const float inv = 1.0f / sum;

    const int d    = tid & 63;
    const int half = tid >> 6;
    float acc = 0.f;
    for (int j = half; j < n; j += 2)
        acc += sc[j] * Vv[base + (size_t)j * D + d];
    o2[tid] = acc;
    __syncthreads();
    if (tid < HD)
        O[base + (size_t)q * D + tid] = (o2[tid] + o2[tid + 64]) * inv;
}

// ---------------------------------------------------------------------------
// Launch
// ---------------------------------------------------------------------------
extern "C" void kernel_launch(void* const* d_in, const int* in_sizes, int n_in,
                              void* d_out, int out_size)
{
    (void)in_sizes; (void)n_in; (void)out_size;
    const int*   x    = (const int*)  d_in[0];
    const float* emb  = (const float*)d_in[1];
    const float* pe   = (const float*)d_in[2];
    const float* ln1g = (const float*)d_in[3];
    const float* ln1b = (const float*)d_in[4];
    const float* wq   = (const float*)d_in[5];
    const float* bq   = (const float*)d_in[6];
    const float* wk   = (const float*)d_in[7];
    const float* bk   = (const float*)d_in[8];
    const float* wv   = (const float*)d_in[9];
    const float* bv   = (const float*)d_in[10];
    const float* wo   = (const float*)d_in[11];
    const float* bo   = (const float*)d_in[12];
    const float* ln2g = (const float*)d_in[13];
    const float* ln2b = (const float*)d_in[14];
    const float* w1   = (const float*)d_in[15];
    const float* b1   = (const float*)d_in[16];
    const float* w2   = (const float*)d_in[17];
    const float* b2   = (const float*)d_in[18];
    const float* lnfg = (const float*)d_in[19];
    const float* lnfb = (const float*)d_in[20];
    const float* wout = (const float*)d_in[21];
    float* out = (float*)d_out;

    float *h, *a, *q, *k, *v, *t, *f;
    cudaGetSymbolAddress((void**)&h, g_h);
    cudaGetSymbolAddress((void**)&a, g_a);
    cudaGetSymbolAddress((void**)&q, g_q);
    cudaGetSymbolAddress((void**)&k, g_k);
    cudaGetSymbolAddress((void**)&v, g_v);
    cudaGetSymbolAddress((void**)&t, g_t);
    cudaGetSymbolAddress((void**)&f, g_f);

    const dim3 gD (D  / 128, M / 128);   // N=1024
    const dim3 gDH(DH / 128, M / 128);   // N=4096
    const dim3 gV (V  / 128, M / 128);   // N=32000
    const dim3 gAttn(S, NH, B);

    embed_kernel<<<M, 256>>>(x, emb, pe, h);

    for (int l = 0; l < NL; l++) {
        const size_t wOff = (size_t)l * D * D;
        ln_kernel<<<M, 256>>>(h, ln1g + l * D, ln1b + l * D, a);
        sgemm128<true, false, false><<<gD, 256>>>(M, D, D, a, wq + wOff, bq + l * D, nullptr, q);
        sgemm128<true, false, false><<<gD, 256>>>(M, D, D, a, wk + wOff, bk + l * D, nullptr, k);
        sgemm128<true, false, false><<<gD, 256>>>(M, D, D, a, wv + wOff, bv + l * D, nullptr, v);
        attn_kernel<<<gAttn, 128>>>(q, k, v, t);
        sgemm128<true, true,  false><<<gD, 256>>>(M, D, D, t, wo + wOff, bo + l * D, h, h);
        ln_kernel<<<M, 256>>>(h, ln2g + l * D, ln2b + l * D, a);
        sgemm128<true, false, true ><<<gDH, 256>>>(M, DH, D, a, w1 + (size_t)l * D * DH, b1 + l * DH, nullptr, f);
        sgemm128<true, true,  false><<<gD, 256>>>(M, D, DH, f, w2 + (size_t)l * DH * D, b2 + l * D, h, h);
    }

    ln_kernel<<<M, 256>>>(h, lnfg, lnfb, a);
    sgemm128<false, false, false><<<gV, 256>>>(M, V, D, a, wout, nullptr, nullptr, out);
}

// round 2
// speedup vs baseline: 4.8916x; 4.8916x over previous
#include <cuda_runtime.h>
#include <cuda_bf16.h>
#include <math.h>
#include <stdint.h>

// Problem constants
constexpr int B  = 2;
constexpr int S  = 1024;
constexpr int V  = 32000;
constexpr int D  = 1024;
constexpr int DH = 4096;
constexpr int NL = 4;
constexpr int NH = 16;
constexpr int HD = 64;
constexpr int M  = B * S;          // 2048 rows everywhere

// ---------------------------------------------------------------------------
// Scratch (device globals — no allocations allowed)
// ---------------------------------------------------------------------------
__device__ float g_h[M * D];       // residual stream
__device__ float g_a[M * D];       // LN output
__device__ float g_q[M * D];
__device__ float g_k[M * D];
__device__ float g_v[M * D];
__device__ float g_t[M * D];       // attention output
__device__ float g_f[M * DH];      // FFN intermediate

// ---------------------------------------------------------------------------
// Embedding + positional encoding
// ---------------------------------------------------------------------------
__global__ void embed_kernel(const int* __restrict__ x,
                             const float* __restrict__ emb,
                             const float* __restrict__ pe,
                             float* __restrict__ out)
{
    const int i   = blockIdx.x;
    const int s   = i % S;
    const int tok = x[i];
    const float4* e = reinterpret_cast<const float4*>(emb + (size_t)tok * D);
    const float4* p = reinterpret_cast<const float4*>(pe  + (size_t)s   * D);
    float4*       o = reinterpret_cast<float4*>(out + (size_t)i * D);
    const int t = threadIdx.x;
    float4 a = e[t], b = p[t];
    o[t] = make_float4(a.x + b.x, a.y + b.y, a.z + b.z, a.w + b.w);
}

// ---------------------------------------------------------------------------
// LayerNorm (row-wise)
// ---------------------------------------------------------------------------
__global__ void ln_kernel(const float* __restrict__ X,
                          const float* __restrict__ gam,
                          const float* __restrict__ bet,
                          float* __restrict__ Y)
{
    const int row = blockIdx.x;
    const float* x = X + (size_t)row * D;
    float*       y = Y + (size_t)row * D;
    __shared__ float sred[8];
    const int tid = threadIdx.x;

    float s = 0.f;
    for (int d = tid; d < D; d += 256) s += x[d];
    #pragma unroll
    for (int o = 16; o > 0; o >>= 1) s += __shfl_xor_sync(0xffffffffu, s, o);
    if ((tid & 31) == 0) sred[tid >> 5] = s;
    __syncthreads();
    float mean = 0.f;
    #pragma unroll
    for (int w = 0; w < 8; w++) mean += sred[w];
    mean *= (1.0f / D);
    __syncthreads();

    float vs = 0.f;
    for (int d = tid; d < D; d += 256) { float t = x[d] - mean; vs += t * t; }
    #pragma unroll
    for (int o = 16; o > 0; o >>= 1) vs += __shfl_xor_sync(0xffffffffu, vs, o);
    if ((tid & 31) == 0) sred[tid >> 5] = vs;
    __syncthreads();
    float var = 0.f;
    #pragma unroll
    for (int w = 0; w < 8; w++) var += sred[w];
    var *= (1.0f / D);
    const float rstd = rsqrtf(var + 1e-5f);

    for (int d = tid; d < D; d += 256)
        y[d] = (x[d] - mean) * rstd * gam[d] + bet[d];
}

// ---------------------------------------------------------------------------
// TF32 tensor-core GEMM: C[M,N] = A[M,K] @ W[K,N] (+bias)(+res)(relu)
// BM=128, BN=128, BK=16; 256 threads = 8 warps (2x4), warp tile 64x32,
// mma.sync.m16n8k8.tf32. Smem padded: A stride 20, B stride 136 (conflict-free).
// All shapes divide tiles exactly.
// ---------------------------------------------------------------------------
__device__ __forceinline__ uint32_t f2tf(float x) {
    uint32_t r;
    asm("cvt.rna.tf32.f32 %0, %1;" : "=r"(r) : "f"(x));
    return r;
}

__device__ __forceinline__ void mma_tf32(float* d,
                                         const uint32_t* a,
                                         const uint32_t* b)
{
    asm volatile(
        "mma.sync.aligned.m16n8k8.row.col.f32.tf32.tf32.f32 "
        "{%0,%1,%2,%3}, {%4,%5,%6,%7}, {%8,%9}, {%0,%1,%2,%3};\n"
        : "+f"(d[0]), "+f"(d[1]), "+f"(d[2]), "+f"(d[3])
        : "r"(a[0]), "r"(a[1]), "r"(a[2]), "r"(a[3]),
          "r"(b[0]), "r"(b[1]));
}

template<bool HAS_BIAS, bool HAS_RES, bool RELU>
__global__ __launch_bounds__(256, 2)
void tgemm(int N, int K,
           const float* __restrict__ A,
           const float* __restrict__ Bm,
           const float* __restrict__ bias,
           const float* __restrict__ res,
           float* __restrict__ C)
{
    constexpr int AS = 20;    // padded A row stride (floats)
    constexpr int BS = 136;   // padded B row stride (floats)
    __shared__ float As[128 * AS];
    __shared__ float Bs[16 * BS];

    const int tid  = threadIdx.x;
    const int lane = tid & 31;
    const int w    = tid >> 5;
    const int wm   = w & 1;           // 0..1 (64-row band)
    const int wn   = w >> 1;          // 0..3 (32-col band)
    const int g    = lane >> 2;       // 0..7
    const int tg   = lane & 3;        // 0..3

    const float* Ag = A  + (size_t)blockIdx.y * 128 * K;
    const float* Bg = Bm + (size_t)blockIdx.x * 128;

    // load index precompute
    const int ar0 = tid >> 2,       ac0 = (tid & 3) * 4;   // A vec tid
    const int br0 = tid >> 5,       bc0 = (tid & 31) * 4;  // B vec tid
    const int ar1 = (tid + 256) >> 2,  ac1 = ((tid + 256) & 3) * 4;
    const int br1 = (tid + 256) >> 5,  bc1 = ((tid + 256) & 31) * 4;

    float acc[4][4][4];
    #pragma unroll
    for (int i = 0; i < 4; i++)
        #pragma unroll
        for (int j = 0; j < 4; j++)
            #pragma unroll
            for (int r = 0; r < 4; r++) acc[i][j][r] = 0.f;

    for (int k0 = 0; k0 < K; k0 += 16) {
        // stage A tile (128x16) as tf32
        {
            float4 a4 = *reinterpret_cast<const float4*>(&Ag[(size_t)ar0 * K + ac0]);
            *reinterpret_cast<uint4*>(&As[ar0 * AS + ac0]) =
                make_uint4(f2tf(a4.x), f2tf(a4.y), f2tf(a4.z), f2tf(a4.w));
            a4 = *reinterpret_cast<const float4*>(&Ag[(size_t)ar1 * K + ac1]);
            *reinterpret_cast<uint4*>(&As[ar1 * AS + ac1]) =
                make_uint4(f2tf(a4.x), f2tf(a4.y), f2tf(a4.z), f2tf(a4.w));
        }
        // stage B tile (16x128) as tf32
        {
            float4 b4 = *reinterpret_cast<const float4*>(&Bg[(size_t)br0 * N + bc0]);
            *reinterpret_cast<uint4*>(&Bs[br0 * BS + bc0]) =
                make_uint4(f2tf(b4.x), f2tf(b4.y), f2tf(b4.z), f2tf(b4.w));
            b4 = *reinterpret_cast<const float4*>(&Bg[(size_t)br1 * N + bc1]);
            *reinterpret_cast<uint4*>(&Bs[br1 * BS + bc1]) =
                make_uint4(f2tf(b4.x), f2tf(b4.y), f2tf(b4.z), f2tf(b4.w));
        }
        __syncthreads();
        Ag += 16;
        Bg += (size_t)16 * N;

        #pragma unroll
        for (int kc = 0; kc < 2; kc++) {
            const int kb = kc * 8;
            uint32_t afrag[4][4], bfrag[4][2];
            #pragma unroll
            for (int mt = 0; mt < 4; mt++) {
                const int rb = wm * 64 + mt * 16;
                afrag[mt][0] = __float_as_uint(As[(rb + g)     * AS + kb + tg]);
                afrag[mt][1] = __float_as_uint(As[(rb + g + 8) * AS + kb + tg]);
                afrag[mt][2] = __float_as_uint(As[(rb + g)     * AS + kb + tg + 4]);
                afrag[mt][3] = __float_as_uint(As[(rb + g + 8) * AS + kb + tg + 4]);
            }
            #pragma unroll
            for (int nt = 0; nt < 4; nt++) {
                const int cb = wn * 32 + nt * 8 + g;
                bfrag[nt][0] = __float_as_uint(Bs[(kb + tg)     * BS + cb]);
                bfrag[nt][1] = __float_as_uint(Bs[(kb + tg + 4) * BS + cb]);
            }
            #pragma unroll
            for (int mt = 0; mt < 4; mt++)
                #pragma unroll
                for (int nt = 0; nt < 4; nt++)
                    mma_tf32(acc[mt][nt], afrag[mt], bfrag[nt]);
        }
        __syncthreads();
    }

    // epilogue
    #pragma unroll
    for (int mt = 0; mt < 4; mt++) {
        const int gr = blockIdx.y * 128 + wm * 64 + mt * 16 + g;
        #pragma unroll
        for (int nt = 0; nt < 4; nt++) {
            const int gc = blockIdx.x * 128 + wn * 32 + nt * 8 + 2 * tg;
            #pragma unroll
            for (int half = 0; half < 2; half++) {
                const size_t base = (size_t)(gr + half * 8) * N + gc;
                float v0 = acc[mt][nt][half * 2 + 0];
                float v1 = acc[mt][nt][half * 2 + 1];
                if (HAS_BIAS) { v0 += bias[gc]; v1 += bias[gc + 1]; }
                if (HAS_RES)  { v0 += res[base]; v1 += res[base + 1]; }
                if (RELU)     { v0 = fmaxf(v0, 0.f); v1 = fmaxf(v1, 0.f); }
                C[base]     = v0;
                C[base + 1] = v1;
            }
        }
    }
}

// ---------------------------------------------------------------------------
// Flash-style causal attention. Tiles 64x64, fp32 FMA, online softmax.
// Block: 256 threads = 16x16 thread grid, 4x4 microtile each.
// Grid: (S/64, NH, B). Q/K/V layout [B,S,D], head h at cols [h*64, h*64+64).
// scale = 1/sqrt(D) = 1/32 (reference scales by sqrt(d_model)).
// ---------------------------------------------------------------------------
__global__ __launch_bounds__(256, 2)
void attn_kernel(const float* __restrict__ Q, const float* __restrict__ K,
                 const float* __restrict__ Vv, float* __restrict__ O)
{
    constexpr int TP = 68;                 // padded tile stride
    __shared__ float Qs[64 * TP];
    __shared__ float Ks[64 * TP];
    __shared__ float Vs[64 * TP];
    __shared__ float Ps[64 * TP];

    const int qt = blockIdx.x, h = blockIdx.y, b = blockIdx.z;
    const int tid = threadIdx.x;
    const int tr = tid >> 4;               // 0..15 (row group)
    const int tc = tid & 15;               // 0..15 (col group)

    const size_t base = (size_t)b * S * D + (size_t)h * HD;
    const float scale = 0.03125f;          // 1/sqrt(1024)

    // load Q tile (scaled)
    #pragma unroll
    for (int p = 0; p < 4; p++) {
        const int v = tid + p * 256;
        const int r = v >> 4, c = (v & 15) * 4;
        float4 q4 = *reinterpret_cast<const float4*>(
            &Q[base + (size_t)(qt * 64 + r) * D + c]);
        Qs[r * TP + c + 0] = q4.x * scale;
        Qs[r * TP + c + 1] = q4.y * scale;
        Qs[r * TP + c + 2] = q4.z * scale;
        Qs[r * TP + c + 3] = q4.w * scale;
    }

    float o[4][4];
    float mi[4], li[4];
    #pragma unroll
    for (int i = 0; i < 4; i++) {
        mi[i] = -INFINITY; li[i] = 0.f;
        #pragma unroll
        for (int j = 0; j < 4; j++) o[i][j] = 0.f;
    }

    for (int kt = 0; kt <= qt; kt++) {
        __syncthreads();   // guard Ks/Vs reuse from previous iteration
        #pragma unroll
        for (int p = 0; p < 4; p++) {
            const int v = tid + p * 256;
            const int r = v >> 4, c = (v & 15) * 4;
            *reinterpret_cast<float4*>(&Ks[r * TP + c]) =
                *reinterpret_cast<const float4*>(&K[base + (size_t)(kt * 64 + r) * D + c]);
            *reinterpret_cast<float4*>(&Vs[r * TP + c]) =
                *reinterpret_cast<const float4*>(&Vv[base + (size_t)(kt * 64 + r) * D + c]);
        }
        __syncthreads();

        // scores: s[i][j] = Q[tr*4+i] . K[tc*4+j]
        float s[4][4];
        #pragma unroll
        for (int i = 0; i < 4; i++)
            #pragma unroll
            for (int j = 0; j < 4; j++) s[i][j] = 0.f;

        for (int d = 0; d < 64; d += 4) {
            float4 q4[4], k4[4];
            #pragma unroll
            for (int i = 0; i < 4; i++)
                q4[i] = *reinterpret_cast<const float4*>(&Qs[(tr * 4 + i) * TP + d]);
            #pragma unroll
            for (int j = 0; j < 4; j++)
                k4[j] = *reinterpret_cast<const float4*>(&Ks[(tc * 4 + j) * TP + d]);
            #pragma unroll
            for (int i = 0; i < 4; i++)
                #pragma unroll
                for (int j = 0; j < 4; j++)
                    s[i][j] += q4[i].x * k4[j].x + q4[i].y * k4[j].y
                             + q4[i].z * k4[j].z + q4[i].w * k4[j].w;
        }

        // causal mask on diagonal tile
        if (kt == qt) {
            #pragma unroll
            for (int i = 0; i < 4; i++)
                #pragma unroll
                for (int j = 0; j < 4; j++)
                    if (tc * 4 + j > tr * 4 + i) s[i][j] = -INFINITY;
        }

        // online softmax update (row reductions across 16-lane tc groups)
        #pragma unroll
        for (int i = 0; i < 4; i++) {
            float rm = fmaxf(fmaxf(s[i][0], s[i][1]), fmaxf(s[i][2], s[i][3]));
            #pragma unroll
            for (int off = 1; off < 16; off <<= 1)
                rm = fmaxf(rm, __shfl_xor_sync(0xffffffffu, rm, off));
            const float mn = fmaxf(mi[i], rm);
            const float sc = __expf(mi[i] - mn);
            float rs = 0.f;
            #pragma unroll
            for (int j = 0; j < 4; j++) {
                const float p = __expf(s[i][j] - mn);
                Ps[(tr * 4 + i) * TP + tc * 4 + j] = p;
                rs += p;
            }
            #pragma unroll
            for (int off = 1; off < 16; off <<= 1)
                rs += __shfl_xor_sync(0xffffffffu, rs, off);
            li[i] = li[i] * sc + rs;
            mi[i] = mn;
            #pragma unroll
            for (int j = 0; j < 4; j++) o[i][j] *= sc;
        }
        __syncthreads();

        // O += P @ V
        for (int k = 0; k < 64; k++) {
            const float4 v4 = *reinterpret_cast<const float4*>(&Vs[k * TP + tc * 4]);
            float pr[4];
            #pragma unroll
            for (int i = 0; i < 4; i++) pr[i] = Ps[(tr * 4 + i) * TP + k];
            #pragma unroll
            for (int i = 0; i < 4; i++) {
                o[i][0] += pr[i] * v4.x;
                o[i][1] += pr[i] * v4.y;
                o[i][2] += pr[i] * v4.z;
                o[i][3] += pr[i] * v4.w;
            }
        }
    }

    // write O
    #pragma unroll
    for (int i = 0; i < 4; i++) {
        const float inv = 1.0f / li[i];
        const int row = qt * 64 + tr * 4 + i;
        float4 r4 = make_float4(o[i][0] * inv, o[i][1] * inv,
                                o[i][2] * inv, o[i][3] * inv);
        *reinterpret_cast<float4*>(&O[base + (size_t)row * D + tc * 4]) = r4;
    }
}

// ---------------------------------------------------------------------------
// Launch
// ---------------------------------------------------------------------------
extern "C" void kernel_launch(void* const* d_in, const int* in_sizes, int n_in,
                              void* d_out, int out_size)
{
    (void)in_sizes; (void)n_in; (void)out_size;
    const int*   x    = (const int*)  d_in[0];
    const float* emb  = (const float*)d_in[1];
    const float* pe   = (const float*)d_in[2];
    const float* ln1g = (const float*)d_in[3];
    const float* ln1b = (const float*)d_in[4];
    const float* wq   = (const float*)d_in[5];
    const float* bq   = (const float*)d_in[6];
    const float* wk   = (const float*)d_in[7];
    const float* bk   = (const float*)d_in[8];
    const float* wv   = (const float*)d_in[9];
    const float* bv   = (const float*)d_in[10];
    const float* wo   = (const float*)d_in[11];
    const float* bo   = (const float*)d_in[12];
    const float* ln2g = (const float*)d_in[13];
    const float* ln2b = (const float*)d_in[14];
    const float* w1   = (const float*)d_in[15];
    const float* b1   = (const float*)d_in[16];
    const float* w2   = (const float*)d_in[17];
    const float* b2   = (const float*)d_in[18];
    const float* lnfg = (const float*)d_in[19];
    const float* lnfb = (const float*)d_in[20];
    const float* wout = (const float*)d_in[21];
    float* out = (float*)d_out;

    float *h, *a, *q, *k, *v, *t, *f;
    cudaGetSymbolAddress((void**)&h, g_h);
    cudaGetSymbolAddress((void**)&a, g_a);
    cudaGetSymbolAddress((void**)&q, g_q);
    cudaGetSymbolAddress((void**)&k, g_k);
    cudaGetSymbolAddress((void**)&v, g_v);
    cudaGetSymbolAddress((void**)&t, g_t);
    cudaGetSymbolAddress((void**)&f, g_f);

    const dim3 gD (D  / 128, M / 128);   // N=1024
    const dim3 gDH(DH / 128, M / 128);   // N=4096
    const dim3 gV (V  / 128, M / 128);   // N=32000
    const dim3 gAttn(S / 64, NH, B);

    embed_kernel<<<M, 256>>>(x, emb, pe, h);

    for (int l = 0; l < NL; l++) {
        const size_t wOff = (size_t)l * D * D;
        ln_kernel<<<M, 256>>>(h, ln1g + l * D, ln1b + l * D, a);
        tgemm<true, false, false><<<gD, 256>>>(D, D, a, wq + wOff, bq + l * D, nullptr, q);
        tgemm<true, false, false><<<gD, 256>>>(D, D, a, wk + wOff, bk + l * D, nullptr, k);
        tgemm<true, false, false><<<gD, 256>>>(D, D, a, wv + wOff, bv + l * D, nullptr, v);
        attn_kernel<<<gAttn, 256>>>(q, k, v, t);
        tgemm<true, true,  false><<<gD, 256>>>(D, D, t, wo + wOff, bo + l * D, h, h);
        ln_kernel<<<M, 256>>>(h, ln2g + l * D, ln2b + l * D, a);
        tgemm<true, false, true ><<<gDH, 256>>>(DH, D, a, w1 + (size_t)l * D * DH, b1 + l * DH, nullptr, f);
        tgemm<true, true,  false><<<gD, 256>>>(D, DH, f, w2 + (size_t)l * DH * D, b2 + l * D, h, h);
    }

    ln_kernel<<<M, 256>>>(h, lnfg, lnfb, a);
    tgemm<false, false, false><<<gV, 256>>>(V, D, a, wout, nullptr, nullptr, out);
}